// round 8
// baseline (speedup 1.0000x reference)
#include <cuda_runtime.h>
#include <stdint.h>

#define D       256
#define MITEMS  16
#define TPB     128
#define ROWS    128            // rows per block, 1 per thread
#define CHUNK   8              // dims per pipeline stage
#define NCH     32
#define QSTR    12             // q smem row stride (words): 8 dims + pad, 16B-aligned,
                               // LDS.128 conflict-free (3t mod 8 distinct within phase)
#define QBUF    (ROWS * QSTR)  // 1536 floats per buffer
#define NBUF    3
#define SM_MEM  (NBUF * QBUF)  // 4608: mem_rm offset
#define SMEM_FLOATS (SM_MEM + MITEMS * D)   // 8704 floats = 34816 B -> 6 blocks/SM
#define SMEM_BYTES  (SMEM_FLOATS * 4)
#define NEG_BIG (-1e30f)

typedef unsigned long long u64;

__device__ __forceinline__ u64 pack2(float lo, float hi) {
    u64 r; asm("mov.b64 %0, {%1, %2};" : "=l"(r) : "f"(lo), "f"(hi)); return r;
}
__device__ __forceinline__ void unpack2(u64 v, float& lo, float& hi) {
    asm("mov.b64 {%0, %1}, %2;" : "=f"(lo), "=f"(hi) : "l"(v));
}
#define FMA2(d, a, b) asm("fma.rn.f32x2 %0, %1, %2, %0;" : "+l"(d) : "l"(a), "l"(b))
#define CP16(dst, src) \
    asm volatile("cp.async.cg.shared.global [%0], [%1], 16;" :: "r"(dst), "l"(src))
#define CPCOMMIT() asm volatile("cp.async.commit_group;")
#define CPWAIT(n)  asm volatile("cp.async.wait_group %0;" :: "n"(n))

__global__ void __launch_bounds__(TPB, 6) epm_kernel(
    const float* __restrict__ q,
    const float* __restrict__ mem,
    float* __restrict__ out_ret,
    float* __restrict__ out_max,
    int nrows)
{
    extern __shared__ __align__(16) float sh[];
    float* qs     = sh;                 // 3 staging buffers
    float* mem_rm = sh + SM_MEM;        // 16 x 256 row-major (dot broadcasts + blend gather)
    float* pw     = sh;                 // aliases qs buf0 after dot (words 0..512)
    int*   pidx   = (int*)(sh + ROWS * 4);   // words 512..640 (still inside buf0)

    const int tid = threadIdx.x;
    const int blockRow = blockIdx.x * ROWS;
    const int nr1 = nrows - 1;
    const uint32_t qs_s = (uint32_t)__cvta_generic_to_shared(qs);

    // cp.async mapping: per chunk 128 rows x 32B = 256 CP16 = 2 per thread
    const int rsub = tid >> 1;     // 0..63
    const int sub  = tid & 1;      // 16B slot

    // ---- stage chunks 0 and 1 immediately (hide DRAM latency behind setup) ----
    #pragma unroll
    for (int c0 = 0; c0 < 2; c0++) {
        #pragma unroll
        for (int j = 0; j < 2; j++) {
            int rl = rsub + 64 * j;
            int rg = blockRow + rl; rg = rg < nr1 ? rg : nr1;
            const float* src = q + (size_t)rg * D + c0 * CHUNK + sub * 4;
            uint32_t dst = qs_s + (uint32_t)(c0 * QBUF + rl * QSTR + sub * 4) * 4u;
            CP16(dst, src);
        }
        CPCOMMIT();
    }

    // ---- load memory bank row-major into smem (coalesced float4 copy) ----
    {
        const float4* src4 = (const float4*)mem;
        float4* dst4 = (float4*)mem_rm;
        #pragma unroll
        for (int i = 0; i < (MITEMS * D / 4) / TPB; i++)    // 8 iters
            dst4[tid + TPB * i] = src4[tid + TPB * i];
    }

    // ---- dot mainloop: dim-pair-packed f32x2, acc[item] over dim pairs ----
    u64 acc[MITEMS];
    #pragma unroll
    for (int m = 0; m < MITEMS; m++) acc[m] = 0ull;
    u64 ssq2 = 0ull;

    const ulonglong2* mb = (const ulonglong2*)mem_rm;   // [item][64 x 16B]

    #pragma unroll 1
    for (int ct = 0; ct < NCH; ct++) {
        // 1) my chunk-ct copies complete (keep ct+1 in flight)
        if (ct + 1 < NCH) { CPWAIT(1); } else { CPWAIT(0); }
        // 2) ALL threads' chunk-ct copies complete; all readers of buf (ct-1)%3 done
        __syncthreads();
        // 3) refill the just-freed buffer (WAR-safe per the barrier above)
        if (ct + 2 < NCH) {
            #pragma unroll
            for (int j = 0; j < 2; j++) {
                int rl = rsub + 64 * j;
                int rg = blockRow + rl; rg = rg < nr1 ? rg : nr1;
                const float* src = q + (size_t)rg * D + (ct + 2) * CHUNK + sub * 4;
                uint32_t dst = qs_s +
                    (uint32_t)(((ct + 2) % NBUF) * QBUF + rl * QSTR + sub * 4) * 4u;
                CP16(dst, src);
            }
            CPCOMMIT();
        }
        // 4) compute chunk ct
        const float* qrow = qs + (ct % NBUF) * QBUF + tid * QSTR;
        ulonglong2 qv = *(const ulonglong2*)(qrow);        // dims +0..3 as 2 pairs
        ulonglong2 qw = *(const ulonglong2*)(qrow + 4);    // dims +4..7
        FMA2(ssq2, qv.x, qv.x); FMA2(ssq2, qv.y, qv.y);
        FMA2(ssq2, qw.x, qw.x); FMA2(ssq2, qw.y, qw.y);

        #pragma unroll
        for (int m = 0; m < MITEMS; m += 2) {
            ulonglong2 a0 = mb[m * 64 + ct * 2];            // mem[m][dims +0..3]
            ulonglong2 a1 = mb[m * 64 + ct * 2 + 1];        // mem[m][dims +4..7]
            ulonglong2 b0 = mb[(m + 1) * 64 + ct * 2];
            ulonglong2 b1 = mb[(m + 1) * 64 + ct * 2 + 1];
            FMA2(acc[m], a0.x, qv.x);     FMA2(acc[m], a0.y, qv.y);
            FMA2(acc[m], a1.x, qw.x);     FMA2(acc[m], a1.y, qw.y);
            FMA2(acc[m + 1], b0.x, qv.x); FMA2(acc[m + 1], b0.y, qv.y);
            FMA2(acc[m + 1], b1.x, qw.x); FMA2(acc[m + 1], b1.y, qw.y);
        }
    }

    // all threads finished reading buf0 (last buf0 chunk = 30; barrier at ct=31 top)
    // but pw writes below race with OTHER threads still computing chunk 31 only via
    // buf 31%3 = 2, never buf0 -> safe to write pw/pidx now.

    // ---- epilogue: hsum pairs, normalize, top-4 (first-index ties), softmax ----
    {
        float s[MITEMS];
        #pragma unroll
        for (int m = 0; m < MITEMS; m++) {
            float lo, hi; unpack2(acc[m], lo, hi);
            s[m] = lo + hi;
        }
        float sl, shi; unpack2(ssq2, sl, shi);
        float ssq = sl + shi;
        float inv = rsqrtf(fmaxf(ssq, 1e-24f)) * 10.0f;   // (1/|q|)/tau; mem rows unit-norm
        #pragma unroll
        for (int m = 0; m < MITEMS; m++) s[m] *= inv;

        float bw[4]; int bi[4];
        #pragma unroll
        for (int k = 0; k < 4; k++) {
            float best = NEG_BIG; int b = 0;
            #pragma unroll
            for (int m = 0; m < MITEMS; m++)
                if (s[m] > best) { best = s[m]; b = m; }   // strict > : first index wins
            bw[k] = best; bi[k] = b;
            #pragma unroll
            for (int m = 0; m < MITEMS; m++)
                s[m] = (m == b) ? NEG_BIG : s[m];
        }
        float e1 = __expf(bw[1] - bw[0]);
        float e2 = __expf(bw[2] - bw[0]);
        float e3 = __expf(bw[3] - bw[0]);
        float rden = 1.0f / (1.0f + e1 + e2 + e3);

        pw[tid * 4 + 0] = rden;
        pw[tid * 4 + 1] = e1 * rden;
        pw[tid * 4 + 2] = e2 * rden;
        pw[tid * 4 + 3] = e3 * rden;
        pidx[tid] = bi[0] | (bi[1] << 4) | (bi[2] << 8) | (bi[3] << 12);

        int row_g = blockRow + tid;
        if (row_g < nrows) out_max[row_g] = bw[0];
    }
    __syncthreads();

    // ---- sparse blend: warp-per-row, slab-split gathers (conflict-free LDS.128) ----
    const int wid  = tid >> 5;
    const int lane = tid & 31;
    #pragma unroll 2
    for (int j = 0; j < ROWS / 4; j++) {         // 32 rows per warp
        int rl = wid * (ROWS / 4) + j;
        int row_g = blockRow + rl;
        float4 w4 = *(const float4*)(pw + rl * 4);     // broadcast, 1 wf
        int pk = pidx[rl];
        u64 W0 = pack2(w4.x, w4.x), W1 = pack2(w4.y, w4.y);
        u64 W2 = pack2(w4.z, w4.z), W3 = pack2(w4.w, w4.w);
        const ulonglong2* r0 = (const ulonglong2*)(mem_rm + ((pk      ) & 15) * D);
        const ulonglong2* r1 = (const ulonglong2*)(mem_rm + ((pk >> 4 ) & 15) * D);
        const ulonglong2* r2 = (const ulonglong2*)(mem_rm + ((pk >> 8 ) & 15) * D);
        const ulonglong2* r3 = (const ulonglong2*)(mem_rm + ((pk >> 12) & 15) * D);

        u64 o0 = 0ull, o1 = 0ull, o2 = 0ull, o3 = 0ull;
        ulonglong2 a;
        a = r0[lane];      FMA2(o0, a.x, W0); FMA2(o1, a.y, W0);
        a = r1[lane];      FMA2(o0, a.x, W1); FMA2(o1, a.y, W1);
        a = r2[lane];      FMA2(o0, a.x, W2); FMA2(o1, a.y, W2);
        a = r3[lane];      FMA2(o0, a.x, W3); FMA2(o1, a.y, W3);
        a = r0[32 + lane]; FMA2(o2, a.x, W0); FMA2(o3, a.y, W0);
        a = r1[32 + lane]; FMA2(o2, a.x, W1); FMA2(o3, a.y, W1);
        a = r2[32 + lane]; FMA2(o2, a.x, W2); FMA2(o3, a.y, W2);
        a = r3[32 + lane]; FMA2(o2, a.x, W3); FMA2(o3, a.y, W3);

        if (row_g < nrows) {
            ulonglong2* op = (ulonglong2*)(out_ret + (size_t)row_g * D);
            ulonglong2 v0; v0.x = o0; v0.y = o1;       // floats 4*lane ..
            ulonglong2 v1; v1.x = o2; v1.y = o3;       // floats 128 + 4*lane ..
            op[lane]      = v0;
            op[32 + lane] = v1;
        }
    }
}

extern "C" void kernel_launch(void* const* d_in, const int* in_sizes, int n_in,
                              void* d_out, int out_size)
{
    const float* q   = (const float*)d_in[0];
    const float* mem = (const float*)d_in[1];
    int nrows = in_sizes[0] / D;              // 131072
    float* out_ret = (float*)d_out;
    float* out_max = out_ret + (size_t)nrows * D;

    cudaFuncSetAttribute(epm_kernel,
                         cudaFuncAttributeMaxDynamicSharedMemorySize, SMEM_BYTES);

    int grid = (nrows + ROWS - 1) / ROWS;     // 1024
    epm_kernel<<<grid, TPB, SMEM_BYTES>>>(q, mem, out_ret, out_max, nrows);
}